// round 2
// baseline (speedup 1.0000x reference)
#include <cuda_runtime.h>
#include <cuda_bf16.h>

// warp3D: out[b,c,d,h,w] = trilinear sample of I at (x,y,z) = (w,h,d) + flow[b,{0,1,2},d,h,w]
// Shapes: I [B,C,D,H,W] f32, flow [B,3,D,H,W] f32, out [B,C,D,H,W] f32.
// Matches the JAX/torch reference exactly, including the clamp-order subtlety:
//   x1 = clamp(floor(x)+1), x0 = clamp(floor(x)); weights use the CLAMPED x1.

#define BB 2
#define CC 2
#define DD 160
#define HH 192
#define WW 224

static constexpr int HW  = HH * WW;          // 43008
static constexpr int DHW = DD * HW;          // 6,881,280
static constexpr int NPT = BB * DHW;         // 13,762,560 sample points

__global__ __launch_bounds__(256)
void warp3d_kernel(const float* __restrict__ I,
                   const float* __restrict__ flow,
                   float* __restrict__ out)
{
    int i = blockIdx.x * blockDim.x + threadIdx.x;
    if (i >= NPT) return;

    // Decompose i -> (b, d, h, w)
    int w = i % WW;
    int t = i / WW;
    int h = t % HH;
    t /= HH;
    int d = t % DD;
    int b = t / DD;

    int s = i - b * DHW;                // spatial index within batch

    const float* fb = flow + (size_t)b * 3 * DHW + s;
    float x = fb[0]        + (float)w;
    float y = fb[DHW]      + (float)h;
    float z = fb[2 * DHW]  + (float)d;

    int x0r = (int)floorf(x);
    int y0r = (int)floorf(y);
    int z0r = (int)floorf(z);

    int x1 = min(max(x0r + 1, 0), WW - 1);
    int y1 = min(max(y0r + 1, 0), HH - 1);
    int z1 = min(max(z0r + 1, 0), DD - 1);
    int x0 = min(max(x0r, 0), WW - 1);
    int y0 = min(max(y0r, 0), HH - 1);
    int z0 = min(max(z0r, 0), DD - 1);

    // Weights from CLAMPED upper corner (matches reference)
    float dx = (float)x1 - x;
    float dy = (float)y1 - y;
    float dz = (float)z1 - z;
    float ex = 1.0f - dx;
    float ey = 1.0f - dy;
    float ez = 1.0f - dz;

    float wa = dz * dx * dy;   // (z0, y0, x0)
    float wb = dz * dx * ey;   // (z0, y1, x0)
    float wc = dz * ex * dy;   // (z0, y0, x1)
    float wd = dz * ex * ey;   // (z0, y1, x1)
    float we = ez * dx * dy;   // (z1, y0, x0)
    float wf = ez * dx * ey;   // (z1, y1, x0)
    float wg = ez * ex * dy;   // (z1, y0, x1)
    float wh = ez * ex * ey;   // (z1, y1, x1)

    const float* Ib0 = I + (size_t)b * CC * DHW;   // channel 0 base for batch b
    const float* Ib1 = Ib0 + DHW;                  // channel 1

    int o000 = z0 * HW + y0 * WW + x0;
    int o010 = z0 * HW + y1 * WW + x0;
    int o001 = z0 * HW + y0 * WW + x1;
    int o011 = z0 * HW + y1 * WW + x1;
    int o100 = z1 * HW + y0 * WW + x0;
    int o110 = z1 * HW + y1 * WW + x0;
    int o101 = z1 * HW + y0 * WW + x1;
    int o111 = z1 * HW + y1 * WW + x1;

    float acc0 = wa * Ib0[o000];
    acc0 = fmaf(wb, Ib0[o010], acc0);
    acc0 = fmaf(wc, Ib0[o001], acc0);
    acc0 = fmaf(wd, Ib0[o011], acc0);
    acc0 = fmaf(we, Ib0[o100], acc0);
    acc0 = fmaf(wf, Ib0[o110], acc0);
    acc0 = fmaf(wg, Ib0[o101], acc0);
    acc0 = fmaf(wh, Ib0[o111], acc0);

    float acc1 = wa * Ib1[o000];
    acc1 = fmaf(wb, Ib1[o010], acc1);
    acc1 = fmaf(wc, Ib1[o001], acc1);
    acc1 = fmaf(wd, Ib1[o011], acc1);
    acc1 = fmaf(we, Ib1[o100], acc1);
    acc1 = fmaf(wf, Ib1[o110], acc1);
    acc1 = fmaf(wg, Ib1[o101], acc1);
    acc1 = fmaf(wh, Ib1[o111], acc1);

    float* ob = out + (size_t)b * CC * DHW + s;
    ob[0]   = acc0;
    ob[DHW] = acc1;
}

extern "C" void kernel_launch(void* const* d_in, const int* in_sizes, int n_in,
                              void* d_out, int out_size)
{
    const float* I    = (const float*)d_in[0];
    const float* flow = (const float*)d_in[1];
    float* out        = (float*)d_out;

    int threads = 256;
    int blocks  = (NPT + threads - 1) / threads;
    warp3d_kernel<<<blocks, threads>>>(I, flow, out);
}